// round 16
// baseline (speedup 1.0000x reference)
#include <cuda_runtime.h>
#include <math.h>

#define NF   24
#define FS   8
#define DY   32
#define DX   32
#define SEQL 300
#define TOTAL (NF*FS*DY*DX*SEQL)   // 58,982,400 floats
#define N4    (TOTAL/4)            // 14,745,600 float4
#define ROW4  75

#define A_THREADS 256
#define A_ILP     4
#define A_BLOCKS  (N4 / (A_THREADS * A_ILP))   // 14400
// stride = 3,686,400 = 75 * 49152 -> idx%75 invariant over ILP slots

#define TAILB     480              // last 480 finishers run the strengthen
#define B_POS     (NF*16*10)       // 3840 positions = TAILB * 8 warps
#define FS_STRIDE (DY*DX*SEQL)     // 307200 floats between fs slices

__device__ float    g_max;    // zero-init; self-reset each run (inputs >= 0)
__device__ unsigned g_done;   // finish tickets; self-reset
__device__ unsigned g_fin;    // tail completion; self-reset

// Hand-evaluated Python bbox math: left = int(32*l), w = int(32*round(l+0.3,4)) - left
__constant__ int c_left[NF] = {
    1, 2, 2, 3, 4, 5, 5, 6, 7, 7, 8, 9,
    9, 10, 11, 12, 12, 13, 14, 14, 15, 16, 16, 17
};
__constant__ int c_w[NF] = {
    10, 9, 10, 10, 9, 9, 10, 10, 9, 10, 10, 9,
    10, 10, 9, 9, 10, 10, 9, 10, 10, 9, 10, 10
};
__constant__ int c_edge_tok[6] = {2, 3, 9, 10, 11, 108};

__device__ __forceinline__ bool sel_tok(int s) {
    return ((unsigned)(s - 9) < 100u) || ((s & ~1) == 2);
}

// normalized gaussian weight for (yrow, xoff) given bbox width w (9 or 10)
__device__ __forceinline__ float gauss_w(int yrow, int xoff, int w) {
    const float dx = (float)yrow * (16.0f / 15.0f) - 8.0f;
    float ax = ((8.0f / 15.0f) * (8.0f / 15.0f) - dx * dx) * (9.0f / 512.0f);
    float dy, dymin2, inv2sy2;
    if (w == 10) {
        dy = (float)xoff * (10.0f / 9.0f) - 5.0f;
        dymin2 = (5.0f / 9.0f) * (5.0f / 9.0f);
        inv2sy2 = 9.0f / 200.0f;
    } else {
        dy = (float)xoff * (9.0f / 8.0f) - 4.0f;
        dymin2 = 0.25f;
        inv2sy2 = 1.0f / 18.0f;
    }
    return __expf(ax + (dymin2 - dy * dy) * inv2sy2);
}

__global__ void __launch_bounds__(A_THREADS, 8)
injector_kernel(const float4* __restrict__ in4, float4* __restrict__ out4,
                const float* __restrict__ in, float* __restrict__ out) {
    const int tid  = threadIdx.x;
    const int lane = tid & 31;
    const int wid  = tid >> 5;

    // ============ pass A: weaken + max (R7 form, multi-wave, 7.1 TB/s) =======
    const int t      = blockIdx.x * A_THREADS + tid;
    const int stride = A_BLOCKS * A_THREADS;

    const int s0 = (t % ROW4) * 4;     // invariant across ILP slots
    float4 m;
    m.x = sel_tok(s0    ) ? 0.918f : 1.0f;
    m.y = sel_tok(s0 + 1) ? 0.918f : 1.0f;
    m.z = sel_tok(s0 + 2) ? 0.918f : 1.0f;
    m.w = sel_tok(s0 + 3) ? 0.918f : 1.0f;

    float4 v[A_ILP];
    #pragma unroll
    for (int k = 0; k < A_ILP; k++) v[k] = __ldcs(in4 + t + k * stride);

    float mx = 0.f;
    #pragma unroll
    for (int k = 0; k < A_ILP; k++) {
        float4 x = v[k];
        mx = fmaxf(mx, fmaxf(fmaxf(x.x, x.y), fmaxf(x.z, x.w)));
        __stcs(out4 + t + k * stride,
               make_float4(x.x * m.x, x.y * m.y, x.z * m.z, x.w * m.w));
    }

    #pragma unroll
    for (int off = 16; off; off >>= 1)
        mx = fmaxf(mx, __shfl_xor_sync(0xffffffffu, mx, off));
    __shared__ float sm[A_THREADS / 32];
    __shared__ unsigned s_ticket;
    if (lane == 0) sm[wid] = mx;
    __syncthreads();
    if (tid < 8) {
        mx = sm[tid];
        #pragma unroll
        for (int off = 4; off; off >>= 1)
            mx = fmaxf(mx, __shfl_xor_sync(0xffu, mx, off));
        if (tid == 0) {
            atomicMax((int*)&g_max, __float_as_int(mx));   // inputs >= 0
            __threadfence();                               // publish before ticket
            s_ticket = atomicAdd(&g_done, 1u);
        }
    }
    __syncthreads();
    const unsigned ticket = s_ticket;

    // ============ tail: last TAILB finishers run the strengthen ==============
    if (ticket < A_BLOCKS - TAILB) return;

    if (tid == 0) {   // wait until every block has published its max
        while (*(volatile unsigned*)&g_done != A_BLOCKS) __nanosleep(32);
    }
    __syncthreads();
    __threadfence();                                       // acquire
    const float gmax = *(volatile float*)&g_max;

    // this block's 8 positions
    const int idx = (int)(ticket - (A_BLOCKS - TAILB));    // [0, 480)
    int pos = idx * 8 + wid;                               // [0, 3840)
    const int xoff = pos % 10;  pos /= 10;
    const int yrow = pos & 15;
    const int f    = pos >> 4;
    const int w    = c_w[f];

    if (xoff < w) {                                        // warp-uniform
        const float add = 0.125f * gauss_w(yrow, xoff, w) * gmax;
        #pragma unroll
        for (int h = 0; h < 2; h++) {
            const long base = (long)((f * FS + h * 4) * DY + 8 + yrow) * DX * SEQL
                            + (long)(c_left[f] + xoff) * SEQL;
            if (lane < 24) {
                const int tok = 12 + 4 * lane;   // 16B-aligned: row*300 ≡ 0 mod 4
                float4 q[4];
                #pragma unroll
                for (int r = 0; r < 4; r++)
                    q[r] = __ldcs((const float4*)(in + base + (long)r * FS_STRIDE + tok));
                #pragma unroll
                for (int r = 0; r < 4; r++)
                    __stcs((float4*)(out + base + (long)r * FS_STRIDE + tok),
                           make_float4(q[r].x + add, q[r].y + add,
                                       q[r].z + add, q[r].w + add));
            } else if (lane < 30) {
                const int tok = c_edge_tok[lane - 24];
                float q[4];
                #pragma unroll
                for (int r = 0; r < 4; r++)
                    q[r] = __ldcs(in + base + (long)r * FS_STRIDE + tok);
                #pragma unroll
                for (int r = 0; r < 4; r++)
                    __stcs(out + base + (long)r * FS_STRIDE + tok, q[r] + add);
            }
        }
    }

    // ============ self-reset for deterministic graph replay ==================
    __syncthreads();
    if (tid == 0) {
        __threadfence();
        unsigned fin = atomicAdd(&g_fin, 1u);
        if (fin == TAILB - 1) {      // last tail block: all reads of g_max done
            g_fin  = 0;
            g_done = 0;
            *(int*)&g_max = 0;       // 0.0f; inputs >= 0
            __threadfence();
        }
    }
}

extern "C" void kernel_launch(void* const* d_in, const int* in_sizes, int n_in,
                              void* d_out, int out_size) {
    const float* in = (const float*)d_in[0];
    float* out = (float*)d_out;
    injector_kernel<<<A_BLOCKS, A_THREADS>>>((const float4*)in, (float4*)out,
                                             in, out);
}